// round 1
// baseline (speedup 1.0000x reference)
#include <cuda_runtime.h>
#include <math.h>

#define HH 128
#define WW 128
#define NN 16384          // H*W
#define BB 2
#define DD 32
#define QQ 128
#define MM 16
#define EPSF 1e-8f

// ---------------- scratch (static device allocations; no cudaMalloc) --------
__device__ float g_feat1[BB*NN*DD];
__device__ float g_feat2[BB*NN*DD];
__device__ float g_k   [BB*NN*DD];
__device__ float g_q   [BB*NN*DD];
__device__ float g_kn  [BB*NN];
__device__ float g_qn  [BB*NN];
__device__ float g_w   [BB*NN*25];   // transposed: [b][pixel][d]
__device__ float g_sum [BB];
__device__ float g_hA  [BB*NN*QQ];
__device__ float g_hB  [BB*NN*QQ];

__global__ void zero_sums_k() {
    if (threadIdx.x < BB) g_sum[threadIdx.x] = 0.f;
}

// ---------------- conv1: (B,H,W,3) -> relu -> (B,H,W,32) --------------------
__global__ void conv1_k(const float* __restrict__ x,
                        const float* __restrict__ w,
                        const float* __restrict__ bias) {
    __shared__ float sw[3*3*3*32];
    __shared__ float sb[32];
    for (int t = threadIdx.x; t < 864; t += 256) sw[t] = w[t];
    if (threadIdx.x < 32) sb[threadIdx.x] = bias[threadIdx.x];
    __syncthreads();

    int gid = blockIdx.x * 8 + (threadIdx.x >> 5);   // pixel in [0, B*N)
    int co  = threadIdx.x & 31;
    int b = gid >> 14, p = gid & (NN-1);
    int i = p >> 7, j = p & 127;

    float acc = sb[co];
    #pragma unroll
    for (int ky = 0; ky < 3; ky++) {
        int yi = i + ky - 1;
        if ((unsigned)yi >= HH) continue;
        #pragma unroll
        for (int kx = 0; kx < 3; kx++) {
            int xj = j + kx - 1;
            if ((unsigned)xj >= WW) continue;
            const float* xp = x + ((size_t)((b << 14) | (yi << 7) | xj)) * 3;
            const float* wp = sw + (ky*3 + kx) * 3 * 32;
            #pragma unroll
            for (int ci = 0; ci < 3; ci++) acc += xp[ci] * wp[ci*32 + co];
        }
    }
    g_feat1[(size_t)gid*32 + co] = fmaxf(acc, 0.f);
}

// ---------------- conv2: (B,H,W,32) -> relu -> (B,H,W,32) -------------------
__global__ void conv2_k(const float* __restrict__ w,
                        const float* __restrict__ bias) {
    __shared__ float sw[3*3*32*32];
    __shared__ float sb[32];
    for (int t = threadIdx.x; t < 9216; t += 256) sw[t] = w[t];
    if (threadIdx.x < 32) sb[threadIdx.x] = bias[threadIdx.x];
    __syncthreads();

    int gid = blockIdx.x * 8 + (threadIdx.x >> 5);
    int co  = threadIdx.x & 31;
    int b = gid >> 14, p = gid & (NN-1);
    int i = p >> 7, j = p & 127;

    float acc = sb[co];
    #pragma unroll
    for (int ky = 0; ky < 3; ky++) {
        int yi = i + ky - 1;
        if ((unsigned)yi >= HH) continue;
        #pragma unroll
        for (int kx = 0; kx < 3; kx++) {
            int xj = j + kx - 1;
            if ((unsigned)xj >= WW) continue;
            const float* fin = g_feat1 + ((size_t)((b << 14) | (yi << 7) | xj)) * 32;
            const float* wp  = sw + (ky*3 + kx) * 32 * 32;
            #pragma unroll
            for (int ci = 0; ci < 32; ci++) acc += fin[ci] * wp[ci*32 + co];
        }
    }
    g_feat2[(size_t)gid*32 + co] = fmaxf(acc, 0.f);
}

// ---------------- k/q projections + per-node norms --------------------------
__global__ void kq_k(const float* __restrict__ wk,
                     const float* __restrict__ bk,
                     const float* __restrict__ wq) {
    __shared__ float swk[1024], swq[1024], sbk[32];
    for (int t = threadIdx.x; t < 1024; t += 256) { swk[t] = wk[t]; swq[t] = wq[t]; }
    if (threadIdx.x < 32) sbk[threadIdx.x] = bk[threadIdx.x];
    __syncthreads();

    int gid = blockIdx.x * 8 + (threadIdx.x >> 5);
    int co  = threadIdx.x & 31;

    const float* f = g_feat2 + (size_t)gid*32;
    float ka = sbk[co], qa = 0.f;
    #pragma unroll
    for (int ci = 0; ci < 32; ci++) {
        float fv = f[ci];
        ka += fv * swk[ci*32 + co];
        qa += fv * swq[ci*32 + co];
    }
    g_k[(size_t)gid*32 + co] = ka;
    g_q[(size_t)gid*32 + co] = qa;

    float ks = ka*ka, qs = qa*qa;
    #pragma unroll
    for (int o = 16; o; o >>= 1) {
        ks += __shfl_xor_sync(0xffffffffu, ks, o);
        qs += __shfl_xor_sync(0xffffffffu, qs, o);
    }
    if (co == 0) { g_kn[gid] = sqrtf(ks); g_qn[gid] = sqrtf(qs); }
}

// ---------------- edge weights: exp(cosine) + per-batch sum -----------------
// scores are cosine similarities in [-1,1]; skipping the softmax max-shift is
// numerically safe (exp range [0.37, 2.72]).
__global__ void edgew_k() {
    int b = blockIdx.y;
    int p = blockIdx.x * 128 + threadIdx.x;
    int i = p >> 7, j = p & 127;
    size_t base = ((size_t)b << 14) + p;

    float qv[32];
    const float* qp = g_q + base*32;
    #pragma unroll
    for (int c = 0; c < 32; c++) qv[c] = qp[c];
    float qn = g_qn[base];

    float loc = 0.f;
    float* wout = g_w + base*25;
    for (int d = 0; d < 25; d++) {
        int di = d/5 - 2, dj = d%5 - 2;
        int ni = min(max(i + di, 0), HH-1);
        int nj = min(max(j + dj, 0), WW-1);
        size_t nb = ((size_t)b << 14) + (ni << 7) + nj;
        const float* kp = g_k + nb*32;
        float s = 0.f;
        #pragma unroll
        for (int c = 0; c < 32; c++) s += qv[c] * kp[c];
        s /= fmaxf(qn * g_kn[nb], EPSF);
        float es = __expf(s);
        wout[d] = es;
        loc += es;
    }
    #pragma unroll
    for (int o = 16; o; o >>= 1) loc += __shfl_xor_sync(0xffffffffu, loc, o);
    __shared__ float red[4];
    if ((threadIdx.x & 31) == 0) red[threadIdx.x >> 5] = loc;
    __syncthreads();
    if (threadIdx.x == 0)
        atomicAdd(&g_sum[b], red[0] + red[1] + red[2] + red[3]);
}

__global__ void scale_k() {
    int b = blockIdx.y;
    int t = blockIdx.x * 256 + threadIdx.x;
    if (t < NN*25) g_w[(size_t)b*NN*25 + t] *= (1.f / g_sum[b]);
}

// ---------------- propagation: weighted 5x5 stencil + L2-normalize ----------
// 8x8 output tile per block, 12x12 halo (clip folded into load). Warp-per-
// pixel, lane = 4 q-channels (float4 LDS). Norm via warp shuffle.
#define PROP_SMEM_FLOATS (144*128 + 64*25)
__global__ void prop_k(const float* __restrict__ hinit, int it) {
    extern __shared__ float sh[];
    float* shw = sh + 144*128;

    const float* hin = (it == 0) ? hinit : ((it & 1) ? g_hA : g_hB);
    float*       hout = (it & 1) ? g_hB : g_hA;

    int b = blockIdx.z;
    int ti0 = blockIdx.y << 3, tj0 = blockIdx.x << 3;
    int tid = threadIdx.x;

    const float* hb = hin + (((size_t)b << 14) << 7);   // b*N*128
    // halo load: 144 pixel rows x 32 float4
    for (int t = tid; t < 144*32; t += 256) {
        int prow = t >> 5, f4 = t & 31;
        int hr = prow / 12, hc = prow - hr*12;
        int gi = min(max(ti0 + hr - 2, 0), HH-1);
        int gj = min(max(tj0 + hc - 2, 0), WW-1);
        ((float4*)sh)[t] = ((const float4*)(hb + ((size_t)((gi << 7) + gj) << 7)))[f4];
    }
    const float* wb = g_w + (((size_t)b << 14)) * 25;
    for (int t = tid; t < 1600; t += 256) {
        int op = t / 25, d = t - op*25;
        int a = op >> 3, c = op & 7;
        shw[t] = wb[(size_t)(((ti0 + a) << 7) | (tj0 + c)) * 25 + d];
    }
    __syncthreads();

    int lane = tid & 31, warp = tid >> 5;
    float* hob = (it & 1) ? g_hB : g_hA;
    hob = hout;  // (kept explicit)
    #pragma unroll 1
    for (int pp = 0; pp < 8; pp++) {
        int op = (warp << 3) + pp;
        int a = op >> 3, c = op & 7;
        float4 acc = make_float4(0.f, 0.f, 0.f, 0.f);
        const float* wr = shw + op*25;
        #pragma unroll
        for (int d = 0; d < 25; d++) {
            int hp = (a + d/5) * 12 + (c + d%5);
            float w = wr[d];
            float4 hv = ((const float4*)sh)[hp*32 + lane];
            acc.x += w * hv.x; acc.y += w * hv.y;
            acc.z += w * hv.z; acc.w += w * hv.w;
        }
        float ss = acc.x*acc.x + acc.y*acc.y + acc.z*acc.z + acc.w*acc.w;
        #pragma unroll
        for (int o = 16; o; o >>= 1) ss += __shfl_xor_sync(0xffffffffu, ss, o);
        float inv = 1.f / (sqrtf(ss) + EPSF);
        acc.x *= inv; acc.y *= inv; acc.z *= inv; acc.w *= inv;
        size_t go = ((size_t)b << 14) + ((ti0 + a) << 7) + (tj0 + c);
        ((float4*)(hob + (go << 7)))[lane] = acc;
    }
}

// ---------------- mask head: h @ w_mask, softmax over M, NCHW out -----------
__global__ void masks_k(const float* __restrict__ wm, float* __restrict__ out) {
    __shared__ float swm[QQ*MM];
    for (int t = threadIdx.x; t < QQ*MM; t += 256) swm[t] = wm[t];
    __syncthreads();

    int gid = blockIdx.x * 256 + threadIdx.x;   // [0, B*N)
    int b = gid >> 14, p = gid & (NN-1);
    const float* hr = g_hB + (size_t)gid * QQ;  // 32 iterations -> final in hB

    float lg[MM];
    #pragma unroll
    for (int m = 0; m < MM; m++) lg[m] = 0.f;
    for (int q = 0; q < QQ; q++) {
        float hv = hr[q];
        #pragma unroll
        for (int m = 0; m < MM; m++) lg[m] += hv * swm[q*MM + m];
    }
    float mx = lg[0];
    #pragma unroll
    for (int m = 1; m < MM; m++) mx = fmaxf(mx, lg[m]);
    float s = 0.f;
    #pragma unroll
    for (int m = 0; m < MM; m++) { lg[m] = __expf(lg[m] - mx); s += lg[m]; }
    float r = 1.f / s;
    #pragma unroll
    for (int m = 0; m < MM; m++)
        out[(((size_t)(b*MM + m)) << 14) + p] = lg[m] * r;
}

// ---------------- launch ----------------------------------------------------
extern "C" void kernel_launch(void* const* d_in, const int* in_sizes, int n_in,
                              void* d_out, int out_size) {
    const float* x    = (const float*)d_in[0];
    // d_in[1] = edges (int32) — edge structure is analytic, unused
    const float* wc1  = (const float*)d_in[2];
    const float* bc1  = (const float*)d_in[3];
    const float* wc2  = (const float*)d_in[4];
    const float* bc2  = (const float*)d_in[5];
    const float* wk   = (const float*)d_in[6];
    const float* bk   = (const float*)d_in[7];
    const float* wq   = (const float*)d_in[8];
    const float* init = (const float*)d_in[9];
    const float* wm   = (const float*)d_in[10];
    float* out = (float*)d_out;

    cudaFuncSetAttribute(prop_k, cudaFuncAttributeMaxDynamicSharedMemorySize,
                         PROP_SMEM_FLOATS * (int)sizeof(float));

    zero_sums_k<<<1, 32>>>();
    conv1_k<<<BB*NN*32/256, 256>>>(x, wc1, bc1);
    conv2_k<<<BB*NN*32/256, 256>>>(wc2, bc2);
    kq_k   <<<BB*NN*32/256, 256>>>(wk, bk, wq);
    edgew_k<<<dim3(NN/128, BB), 128>>>();
    scale_k<<<dim3(NN*25/256, BB), 256>>>();

    for (int it = 0; it < 32; it++) {
        prop_k<<<dim3(WW/8, HH/8, BB), 256,
                 PROP_SMEM_FLOATS * sizeof(float)>>>(init, it);
    }
    masks_k<<<BB*NN/256, 256>>>(wm, out);
}

// round 2
// speedup vs baseline: 1.2941x; 1.2941x over previous
#include <cuda_runtime.h>
#include <math.h>

#define HH 128
#define WW 128
#define NN 16384          // H*W
#define BB 2
#define DD 32
#define QQ 128
#define MM 16
#define EPSF 1e-8f

// ---------------- scratch (static device allocations; no cudaMalloc) --------
__device__ float g_feat1[BB*NN*DD];
__device__ float g_feat2[BB*NN*DD];
__device__ float g_k   [BB*NN*DD];
__device__ float g_q   [BB*NN*DD];
__device__ float g_kn  [BB*NN];
__device__ float g_qn  [BB*NN];
__device__ float g_w   [BB*NN*25];   // transposed: [b][pixel][d]
__device__ float g_sum [BB];
__device__ float g_hA  [BB*NN*QQ];
__device__ float g_hB  [BB*NN*QQ];

__global__ void zero_sums_k() {
    if (threadIdx.x < BB) g_sum[threadIdx.x] = 0.f;
}

// ---------------- conv1: (B,H,W,3) -> relu -> (B,H,W,32) --------------------
__global__ void conv1_k(const float* __restrict__ x,
                        const float* __restrict__ w,
                        const float* __restrict__ bias) {
    __shared__ float sw[3*3*3*32];
    __shared__ float sb[32];
    for (int t = threadIdx.x; t < 864; t += 512) sw[t] = w[t];
    if (threadIdx.x < 32) sb[threadIdx.x] = bias[threadIdx.x];
    __syncthreads();

    int gid = blockIdx.x * 16 + (threadIdx.x >> 5);   // pixel in [0, B*N)
    int co  = threadIdx.x & 31;
    int b = gid >> 14, p = gid & (NN-1);
    int i = p >> 7, j = p & 127;

    float acc = sb[co];
    #pragma unroll
    for (int ky = 0; ky < 3; ky++) {
        int yi = i + ky - 1;
        if ((unsigned)yi >= HH) continue;
        #pragma unroll
        for (int kx = 0; kx < 3; kx++) {
            int xj = j + kx - 1;
            if ((unsigned)xj >= WW) continue;
            const float* xp = x + ((size_t)((b << 14) | (yi << 7) | xj)) * 3;
            const float* wp = sw + (ky*3 + kx) * 3 * 32;
            #pragma unroll
            for (int ci = 0; ci < 3; ci++) acc += xp[ci] * wp[ci*32 + co];
        }
    }
    g_feat1[(size_t)gid*32 + co] = fmaxf(acc, 0.f);
}

// ---------------- conv2: (B,H,W,32) -> relu -> (B,H,W,32) -------------------
__global__ void conv2_k(const float* __restrict__ w,
                        const float* __restrict__ bias) {
    __shared__ float sw[3*3*32*32];
    __shared__ float sb[32];
    for (int t = threadIdx.x; t < 9216; t += 512) sw[t] = w[t];
    if (threadIdx.x < 32) sb[threadIdx.x] = bias[threadIdx.x];
    __syncthreads();

    int gid = blockIdx.x * 16 + (threadIdx.x >> 5);
    int co  = threadIdx.x & 31;
    int b = gid >> 14, p = gid & (NN-1);
    int i = p >> 7, j = p & 127;

    float acc = sb[co];
    #pragma unroll
    for (int ky = 0; ky < 3; ky++) {
        int yi = i + ky - 1;
        if ((unsigned)yi >= HH) continue;
        #pragma unroll
        for (int kx = 0; kx < 3; kx++) {
            int xj = j + kx - 1;
            if ((unsigned)xj >= WW) continue;
            const float* fin = g_feat1 + ((size_t)((b << 14) | (yi << 7) | xj)) * 32;
            const float* wp  = sw + (ky*3 + kx) * 32 * 32;
            #pragma unroll
            for (int ci = 0; ci < 32; ci++) acc += fin[ci] * wp[ci*32 + co];
        }
    }
    g_feat2[(size_t)gid*32 + co] = fmaxf(acc, 0.f);
}

// ---------------- k/q projections + per-node norms --------------------------
__global__ void kq_k(const float* __restrict__ wk,
                     const float* __restrict__ bk,
                     const float* __restrict__ wq) {
    __shared__ float swk[1024], swq[1024], sbk[32];
    for (int t = threadIdx.x; t < 1024; t += 512) { swk[t] = wk[t]; swq[t] = wq[t]; }
    if (threadIdx.x < 32) sbk[threadIdx.x] = bk[threadIdx.x];
    __syncthreads();

    int gid = blockIdx.x * 16 + (threadIdx.x >> 5);
    int co  = threadIdx.x & 31;

    // one coalesced load per lane, then shuffle-broadcast (kills the 32x
    // broadcast-LDG pattern that made this kernel L1-bound)
    float fv = g_feat2[(size_t)gid*32 + co];
    float ka = sbk[co], qa = 0.f;
    #pragma unroll
    for (int ci = 0; ci < 32; ci++) {
        float f = __shfl_sync(0xffffffffu, fv, ci);
        ka += f * swk[ci*32 + co];
        qa += f * swq[ci*32 + co];
    }
    g_k[(size_t)gid*32 + co] = ka;
    g_q[(size_t)gid*32 + co] = qa;

    float ks = ka*ka, qs = qa*qa;
    #pragma unroll
    for (int o = 16; o; o >>= 1) {
        ks += __shfl_xor_sync(0xffffffffu, ks, o);
        qs += __shfl_xor_sync(0xffffffffu, qs, o);
    }
    if (co == 0) { g_kn[gid] = sqrtf(ks); g_qn[gid] = sqrtf(qs); }
}

// ---------------- edge weights: exp(cosine) + per-batch sum -----------------
__global__ void edgew_k() {
    int b = blockIdx.y;
    int p = blockIdx.x * 128 + threadIdx.x;
    int i = p >> 7, j = p & 127;
    size_t base = ((size_t)b << 14) + p;

    float qv[32];
    const float* qp = g_q + base*32;
    #pragma unroll
    for (int c = 0; c < 32; c++) qv[c] = qp[c];
    float qn = g_qn[base];

    float loc = 0.f;
    float* wout = g_w + base*25;
    for (int d = 0; d < 25; d++) {
        int di = d/5 - 2, dj = d%5 - 2;
        int ni = min(max(i + di, 0), HH-1);
        int nj = min(max(j + dj, 0), WW-1);
        size_t nb = ((size_t)b << 14) + (ni << 7) + nj;
        const float* kp = g_k + nb*32;
        float s = 0.f;
        #pragma unroll
        for (int c = 0; c < 32; c++) s += qv[c] * kp[c];
        s /= fmaxf(qn * g_kn[nb], EPSF);
        float es = __expf(s);
        wout[d] = es;
        loc += es;
    }
    #pragma unroll
    for (int o = 16; o; o >>= 1) loc += __shfl_xor_sync(0xffffffffu, loc, o);
    __shared__ float red[4];
    if ((threadIdx.x & 31) == 0) red[threadIdx.x >> 5] = loc;
    __syncthreads();
    if (threadIdx.x == 0)
        atomicAdd(&g_sum[b], red[0] + red[1] + red[2] + red[3]);
}

__global__ void scale_k() {
    int b = blockIdx.y;
    int t = blockIdx.x * 256 + threadIdx.x;
    if (t < NN*25) g_w[(size_t)b*NN*25 + t] *= (1.f / g_sum[b]);
}

// ---------------- propagation: weighted 5x5 stencil + L2-normalize ----------
// 8x8 tile / block, 12x12x128 halo in smem. Each warp owns ONE tile column
// and accumulates all 8 output rows while sliding down the 12 halo rows:
// every halo float4 is loaded ONCE and reused for up to 5 outputs
// (60 LDS.128/warp instead of 200). FMAs use packed fma.rn.f32x2.
#define PROP_SMEM_FLOATS (144*128 + 64*25)
__global__ __launch_bounds__(256, 2) void prop_k(const float* __restrict__ hinit, int it) {
    extern __shared__ float sh[];
    float* shw = sh + 144*128;

    const float* hin = (it == 0) ? hinit : ((it & 1) ? g_hA : g_hB);
    float*       hout = (it & 1) ? g_hB : g_hA;

    int b = blockIdx.z;
    int ti0 = blockIdx.y << 3, tj0 = blockIdx.x << 3;
    int tid = threadIdx.x;

    const float* hb = hin + ((size_t)b << 21);   // b*N*128
    for (int t = tid; t < 144*32; t += 256) {
        int prow = t >> 5, f4 = t & 31;
        int hr = prow / 12, hc = prow - hr*12;
        int gi = min(max(ti0 + hr - 2, 0), HH-1);
        int gj = min(max(tj0 + hc - 2, 0), WW-1);
        ((float4*)sh)[t] = ((const float4*)(hb + ((size_t)((gi << 7) + gj) << 7)))[f4];
    }
    const float* wb = g_w + ((size_t)b << 14) * 25;
    for (int t = tid; t < 1600; t += 256) {
        int op = t / 25, d = t - op*25;
        int a = op >> 3, cc = op & 7;
        shw[t] = wb[(size_t)(((ti0 + a) << 7) | (tj0 + cc)) * 25 + d];
    }
    __syncthreads();

    int lane = tid & 31, c = tid >> 5;     // warp = tile column

    unsigned long long a01[8], a23[8];
    #pragma unroll
    for (int a = 0; a < 8; a++) { a01[a] = 0ull; a23[a] = 0ull; }

    #pragma unroll
    for (int dj = 0; dj < 5; dj++) {
        int hc = c + dj;
        #pragma unroll
        for (int hr = 0; hr < 12; hr++) {
            float4 hv = ((const float4*)sh)[(hr*12 + hc)*32 + lane];
            unsigned long long h01, h23;
            asm("mov.b64 %0, {%1,%2};" : "=l"(h01) : "f"(hv.x), "f"(hv.y));
            asm("mov.b64 %0, {%1,%2};" : "=l"(h23) : "f"(hv.z), "f"(hv.w));
            #pragma unroll
            for (int a = 0; a < 8; a++) {
                if (a > hr || a + 4 < hr) continue;      // compile-time pruned
                float w = shw[(a*8 + c)*25 + (hr - a)*5 + dj];
                unsigned long long ww;
                asm("mov.b64 %0, {%1,%1};" : "=l"(ww) : "f"(w));
                asm("fma.rn.f32x2 %0, %1, %2, %0;" : "+l"(a01[a]) : "l"(h01), "l"(ww));
                asm("fma.rn.f32x2 %0, %1, %2, %0;" : "+l"(a23[a]) : "l"(h23), "l"(ww));
            }
        }
    }

    float* hob = hout + ((size_t)b << 21);
    #pragma unroll
    for (int a = 0; a < 8; a++) {
        float x0, y0, z0, w0;
        asm("mov.b64 {%0,%1}, %2;" : "=f"(x0), "=f"(y0) : "l"(a01[a]));
        asm("mov.b64 {%0,%1}, %2;" : "=f"(z0), "=f"(w0) : "l"(a23[a]));
        float ss = x0*x0 + y0*y0 + z0*z0 + w0*w0;
        #pragma unroll
        for (int o = 16; o; o >>= 1) ss += __shfl_xor_sync(0xffffffffu, ss, o);
        float inv = 1.f / (sqrtf(ss) + EPSF);
        float4 r = make_float4(x0*inv, y0*inv, z0*inv, w0*inv);
        ((float4*)(hob + ((size_t)(((ti0 + a) << 7) | (tj0 + c)) << 7)))[lane] = r;
    }
}

// ---------------- mask head: h @ w_mask, softmax over M, NCHW out -----------
__global__ void masks_k(const float* __restrict__ wm, float* __restrict__ out) {
    __shared__ float swm[QQ*MM];
    for (int t = threadIdx.x; t < QQ*MM; t += 256) swm[t] = wm[t];
    __syncthreads();

    int gid = blockIdx.x * 256 + threadIdx.x;   // [0, B*N)
    int b = gid >> 14, p = gid & (NN-1);
    const float* hr = g_hB + (size_t)gid * QQ;  // 32 iterations -> final in hB

    float lg[MM];
    #pragma unroll
    for (int m = 0; m < MM; m++) lg[m] = 0.f;
    for (int q = 0; q < QQ; q++) {
        float hv = hr[q];
        #pragma unroll
        for (int m = 0; m < MM; m++) lg[m] += hv * swm[q*MM + m];
    }
    float mx = lg[0];
    #pragma unroll
    for (int m = 1; m < MM; m++) mx = fmaxf(mx, lg[m]);
    float s = 0.f;
    #pragma unroll
    for (int m = 0; m < MM; m++) { lg[m] = __expf(lg[m] - mx); s += lg[m]; }
    float r = 1.f / s;
    #pragma unroll
    for (int m = 0; m < MM; m++)
        out[(((size_t)(b*MM + m)) << 14) + p] = lg[m] * r;
}

// ---------------- launch ----------------------------------------------------
extern "C" void kernel_launch(void* const* d_in, const int* in_sizes, int n_in,
                              void* d_out, int out_size) {
    const float* x    = (const float*)d_in[0];
    // d_in[1] = edges (int32) — edge structure is analytic, unused
    const float* wc1  = (const float*)d_in[2];
    const float* bc1  = (const float*)d_in[3];
    const float* wc2  = (const float*)d_in[4];
    const float* bc2  = (const float*)d_in[5];
    const float* wk   = (const float*)d_in[6];
    const float* bk   = (const float*)d_in[7];
    const float* wq   = (const float*)d_in[8];
    const float* init = (const float*)d_in[9];
    const float* wm   = (const float*)d_in[10];
    float* out = (float*)d_out;

    cudaFuncSetAttribute(prop_k, cudaFuncAttributeMaxDynamicSharedMemorySize,
                         PROP_SMEM_FLOATS * (int)sizeof(float));

    zero_sums_k<<<1, 32>>>();
    conv1_k<<<BB*NN*32/512, 512>>>(x, wc1, bc1);
    conv2_k<<<BB*NN*32/512, 512>>>(wc2, bc2);
    kq_k   <<<BB*NN*32/512, 512>>>(wk, bk, wq);
    edgew_k<<<dim3(NN/128, BB), 128>>>();
    scale_k<<<dim3(NN*25/256, BB), 256>>>();

    for (int it = 0; it < 32; it++) {
        prop_k<<<dim3(WW/8, HH/8, BB), 256,
                 PROP_SMEM_FLOATS * sizeof(float)>>>(init, it);
    }
    masks_k<<<BB*NN/256, 256>>>(wm, out);
}

// round 3
// speedup vs baseline: 1.4381x; 1.1113x over previous
#include <cuda_runtime.h>
#include <math.h>

#define HH 128
#define WW 128
#define NN 16384          // H*W
#define BB 2
#define DD 32
#define QQ 128
#define MM 16
#define EPSF 1e-8f

// ---------------- scratch (static device allocations; no cudaMalloc) --------
__device__ float g_feat1[BB*NN*DD];
__device__ float g_k   [BB*NN*DD];   // pre-normalized k-hat
__device__ float g_q   [BB*NN*DD];   // pre-normalized q-hat
__device__ float g_w   [BB*NN*25];   // unnormalized exp(cos) weights, [b][pixel][tap]
__device__ float g_hA  [BB*NN*QQ];
__device__ float g_hB  [BB*NN*QQ];

// ---------------- conv1: (B,H,W,3) -> relu -> (B,H,W,32) --------------------
__global__ void conv1_k(const float* __restrict__ x,
                        const float* __restrict__ w,
                        const float* __restrict__ bias) {
    __shared__ float sw[3*3*3*32];
    __shared__ float sb[32];
    for (int t = threadIdx.x; t < 864; t += 512) sw[t] = w[t];
    if (threadIdx.x < 32) sb[threadIdx.x] = bias[threadIdx.x];
    __syncthreads();

    int gid = blockIdx.x * 16 + (threadIdx.x >> 5);   // pixel in [0, B*N)
    int co  = threadIdx.x & 31;
    int b = gid >> 14, p = gid & (NN-1);
    int i = p >> 7, j = p & 127;

    float acc = sb[co];
    #pragma unroll
    for (int ky = 0; ky < 3; ky++) {
        int yi = i + ky - 1;
        if ((unsigned)yi >= HH) continue;
        #pragma unroll
        for (int kx = 0; kx < 3; kx++) {
            int xj = j + kx - 1;
            if ((unsigned)xj >= WW) continue;
            const float* xp = x + ((size_t)((b << 14) | (yi << 7) | xj)) * 3;
            const float* wp = sw + (ky*3 + kx) * 3 * 32;
            #pragma unroll
            for (int ci = 0; ci < 3; ci++) acc += xp[ci] * wp[ci*32 + co];
        }
    }
    g_feat1[(size_t)gid*32 + co] = fmaxf(acc, 0.f);
}

// ------- conv2 + fused k/q projection + normalization (k-hat, q-hat) --------
__global__ void conv2kq_k(const float* __restrict__ w,
                          const float* __restrict__ bias,
                          const float* __restrict__ wk,
                          const float* __restrict__ bk,
                          const float* __restrict__ wq) {
    __shared__ float sw[3*3*32*32];
    __shared__ float swk[1024], swq[1024];
    __shared__ float sb[32], sbk[32];
    for (int t = threadIdx.x; t < 9216; t += 512) sw[t] = w[t];
    for (int t = threadIdx.x; t < 1024; t += 512) { swk[t] = wk[t]; swq[t] = wq[t]; }
    if (threadIdx.x < 32) { sb[threadIdx.x] = bias[threadIdx.x]; sbk[threadIdx.x] = bk[threadIdx.x]; }
    __syncthreads();

    int gid = blockIdx.x * 16 + (threadIdx.x >> 5);
    int co  = threadIdx.x & 31;
    int b = gid >> 14, p = gid & (NN-1);
    int i = p >> 7, j = p & 127;

    float acc = sb[co];
    #pragma unroll
    for (int ky = 0; ky < 3; ky++) {
        int yi = i + ky - 1;
        if ((unsigned)yi >= HH) continue;
        #pragma unroll
        for (int kx = 0; kx < 3; kx++) {
            int xj = j + kx - 1;
            if ((unsigned)xj >= WW) continue;
            const float* fin = g_feat1 + ((size_t)((b << 14) | (yi << 7) | xj)) * 32;
            const float* wp  = sw + (ky*3 + kx) * 32 * 32;
            #pragma unroll
            for (int ci = 0; ci < 32; ci++) acc += fin[ci] * wp[ci*32 + co];
        }
    }
    float fv = fmaxf(acc, 0.f);          // feat2 value for channel co (stays in reg)

    float ka = sbk[co], qa = 0.f;
    #pragma unroll
    for (int ci = 0; ci < 32; ci++) {
        float f = __shfl_sync(0xffffffffu, fv, ci);
        ka += f * swk[ci*32 + co];
        qa += f * swq[ci*32 + co];
    }
    float ks = ka*ka, qs = qa*qa;
    #pragma unroll
    for (int o = 16; o; o >>= 1) {
        ks += __shfl_xor_sync(0xffffffffu, ks, o);
        qs += __shfl_xor_sync(0xffffffffu, qs, o);
    }
    // pre-normalize: cosine sim becomes a plain dot product downstream.
    float kinv = rsqrtf(fmaxf(ks, 1e-30f));
    float qinv = rsqrtf(fmaxf(qs, 1e-30f));
    g_k[(size_t)gid*32 + co] = ka * kinv;
    g_q[(size_t)gid*32 + co] = qa * qinv;
}

// ---------------- edge weights: exp(dot(q-hat, k-hat)), tile-based ----------
// 8x8 pixel tile, 12x12 k-halo transposed into smem (stride 145 kills bank
// conflicts). lane = tap (25 of 32 active). Softmax denominator omitted: it is
// a global per-batch constant that cancels in the downstream L2 normalization.
__global__ void edgew_k() {
    __shared__ float sk[32*145];    // [c][halo_pixel], padded stride
    __shared__ float sq[64*32];     // [tile_pixel][c]

    int b = blockIdx.z;
    int ti0 = blockIdx.y << 3, tj0 = blockIdx.x << 3;
    int tid = threadIdx.x;
    size_t bbase = (size_t)b << 14;

    // k halo: 144 pixels x 32 ch, transposed on the fly
    for (int t = tid; t < 1152; t += 256) {
        int hp = t >> 3, c4 = t & 7;
        int hr = hp / 12, hc = hp - hr*12;
        int gi = min(max(ti0 + hr - 2, 0), HH-1);
        int gj = min(max(tj0 + hc - 2, 0), WW-1);
        float4 v = ((const float4*)(g_k + (bbase + (gi << 7) + gj) * 32))[c4];
        sk[(c4*4+0)*145 + hp] = v.x;
        sk[(c4*4+1)*145 + hp] = v.y;
        sk[(c4*4+2)*145 + hp] = v.z;
        sk[(c4*4+3)*145 + hp] = v.w;
    }
    // q tile: 64 pixels x 32 ch, straight
    for (int t = tid; t < 512; t += 256) {
        int p = t >> 3, c4 = t & 7;
        int gi = ti0 + (p >> 3), gj = tj0 + (p & 7);
        ((float4*)sq)[t] = ((const float4*)(g_q + (bbase + (gi << 7) + gj) * 32))[c4];
    }
    __syncthreads();

    int lane = tid & 31, a = tid >> 5;          // warp = tile row a
    int d = min(lane, 24);
    int dr = d / 5, dc = d - dr*5;

    for (int cc = 0; cc < 8; cc++) {
        int p = a*8 + cc;
        int hidx = (a + dr)*12 + (cc + dc);
        const float* skp = sk + hidx;
        const float* sqp = sq + p*32;
        float s = 0.f;
        #pragma unroll
        for (int c = 0; c < 32; c++) s += sqp[c] * skp[c*145];
        if (lane < 25) {
            size_t gp = bbase + ((ti0 + a) << 7) + (tj0 + cc);
            g_w[gp*25 + lane] = __expf(s);
        }
    }
}

// ---------------- propagation: weighted 5x5 stencil + L2-normalize ----------
// 8x8 tile / block, 12x12x128 halo in smem. Warp owns one tile column and
// slides down 12 halo rows, accumulating all 8 output rows (each halo float4
// loaded once, reused up to 5x). Weights staged pre-duplicated as (w,w) so
// the inner loop is LDS.64 -> fma.rn.f32x2 with no packing MOVs.
#define PROP_SMEM_FLOATS (144*128 + 64*25*2)
__global__ __launch_bounds__(256, 2) void prop_k(const float* __restrict__ hinit, int it) {
    extern __shared__ float sh[];
    float* shw = sh + 144*128;                       // float2 (w,w) entries

    const float* hin = (it == 0) ? hinit : ((it & 1) ? g_hA : g_hB);
    float*       hout = (it & 1) ? g_hB : g_hA;

    int b = blockIdx.z;
    int ti0 = blockIdx.y << 3, tj0 = blockIdx.x << 3;
    int tid = threadIdx.x;

    const float* hb = hin + ((size_t)b << 21);       // b*N*128
    for (int t = tid; t < 144*32; t += 256) {
        int prow = t >> 5, f4 = t & 31;
        int hr = prow / 12, hc = prow - hr*12;
        int gi = min(max(ti0 + hr - 2, 0), HH-1);
        int gj = min(max(tj0 + hc - 2, 0), WW-1);
        ((float4*)sh)[t] = ((const float4*)(hb + ((size_t)((gi << 7) + gj) << 7)))[f4];
    }
    const float* wb = g_w + ((size_t)b << 14) * 25;
    for (int t = tid; t < 1600; t += 256) {
        int op = t / 25, d = t - op*25;
        int a = op >> 3, cc = op & 7;
        float w = wb[(size_t)(((ti0 + a) << 7) | (tj0 + cc)) * 25 + d];
        ((float2*)shw)[t] = make_float2(w, w);
    }
    __syncthreads();

    int lane = tid & 31, c = tid >> 5;               // warp = tile column
    const unsigned long long* shw64 = (const unsigned long long*)shw;

    unsigned long long a01[8], a23[8];
    #pragma unroll
    for (int a = 0; a < 8; a++) { a01[a] = 0ull; a23[a] = 0ull; }

    #pragma unroll
    for (int dj = 0; dj < 5; dj++) {
        int hc = c + dj;
        #pragma unroll
        for (int hr = 0; hr < 12; hr++) {
            float4 hv = ((const float4*)sh)[(hr*12 + hc)*32 + lane];
            unsigned long long h01, h23;
            asm("mov.b64 %0, {%1,%2};" : "=l"(h01) : "f"(hv.x), "f"(hv.y));
            asm("mov.b64 %0, {%1,%2};" : "=l"(h23) : "f"(hv.z), "f"(hv.w));
            #pragma unroll
            for (int a = 0; a < 8; a++) {
                if (a > hr || a + 4 < hr) continue;      // compile-time pruned
                unsigned long long ww = shw64[(a*8 + c)*25 + (hr - a)*5 + dj];
                asm("fma.rn.f32x2 %0, %1, %2, %0;" : "+l"(a01[a]) : "l"(h01), "l"(ww));
                asm("fma.rn.f32x2 %0, %1, %2, %0;" : "+l"(a23[a]) : "l"(h23), "l"(ww));
            }
        }
    }

    float* hob = hout + ((size_t)b << 21);
    #pragma unroll
    for (int a = 0; a < 8; a++) {
        float x0, y0, z0, w0;
        asm("mov.b64 {%0,%1}, %2;" : "=f"(x0), "=f"(y0) : "l"(a01[a]));
        asm("mov.b64 {%0,%1}, %2;" : "=f"(z0), "=f"(w0) : "l"(a23[a]));
        float ss = x0*x0 + y0*y0 + z0*z0 + w0*w0;
        #pragma unroll
        for (int o = 16; o; o >>= 1) ss += __shfl_xor_sync(0xffffffffu, ss, o);
        float inv = 1.f / (sqrtf(ss) + EPSF);
        float4 r = make_float4(x0*inv, y0*inv, z0*inv, w0*inv);
        ((float4*)(hob + ((size_t)(((ti0 + a) << 7) | (tj0 + c)) << 7)))[lane] = r;
    }
}

// ---------------- mask head: h @ w_mask, softmax over M, NCHW out -----------
__global__ void masks_k(const float* __restrict__ wm, float* __restrict__ out) {
    __shared__ float swm[QQ*MM];
    for (int t = threadIdx.x; t < QQ*MM; t += 256) swm[t] = wm[t];
    __syncthreads();

    int gid = blockIdx.x * 256 + threadIdx.x;   // [0, B*N)
    int b = gid >> 14, p = gid & (NN-1);
    const float* hr = g_hB + (size_t)gid * QQ;  // 32 iterations -> final in hB

    float lg[MM];
    #pragma unroll
    for (int m = 0; m < MM; m++) lg[m] = 0.f;
    for (int q = 0; q < QQ; q++) {
        float hv = hr[q];
        #pragma unroll
        for (int m = 0; m < MM; m++) lg[m] += hv * swm[q*MM + m];
    }
    float mx = lg[0];
    #pragma unroll
    for (int m = 1; m < MM; m++) mx = fmaxf(mx, lg[m]);
    float s = 0.f;
    #pragma unroll
    for (int m = 0; m < MM; m++) { lg[m] = __expf(lg[m] - mx); s += lg[m]; }
    float r = 1.f / s;
    #pragma unroll
    for (int m = 0; m < MM; m++)
        out[(((size_t)(b*MM + m)) << 14) + p] = lg[m] * r;
}

// ---------------- launch ----------------------------------------------------
extern "C" void kernel_launch(void* const* d_in, const int* in_sizes, int n_in,
                              void* d_out, int out_size) {
    const float* x    = (const float*)d_in[0];
    // d_in[1] = edges (int32) — edge structure is analytic, unused
    const float* wc1  = (const float*)d_in[2];
    const float* bc1  = (const float*)d_in[3];
    const float* wc2  = (const float*)d_in[4];
    const float* bc2  = (const float*)d_in[5];
    const float* wk   = (const float*)d_in[6];
    const float* bk   = (const float*)d_in[7];
    const float* wq   = (const float*)d_in[8];
    const float* init = (const float*)d_in[9];
    const float* wm   = (const float*)d_in[10];
    float* out = (float*)d_out;

    cudaFuncSetAttribute(prop_k, cudaFuncAttributeMaxDynamicSharedMemorySize,
                         PROP_SMEM_FLOATS * (int)sizeof(float));

    conv1_k  <<<BB*NN*32/512, 512>>>(x, wc1, bc1);
    conv2kq_k<<<BB*NN*32/512, 512>>>(wc2, bc2, wk, bk, wq);
    edgew_k  <<<dim3(WW/8, HH/8, BB), 256>>>();

    for (int it = 0; it < 32; it++) {
        prop_k<<<dim3(WW/8, HH/8, BB), 256,
                 PROP_SMEM_FLOATS * sizeof(float)>>>(init, it);
    }
    masks_k<<<BB*NN/256, 256>>>(wm, out);
}

// round 4
// speedup vs baseline: 1.6748x; 1.1646x over previous
#include <cuda_runtime.h>
#include <math.h>

#define HH 128
#define WW 128
#define NN 16384          // H*W
#define BB 2
#define DD 32
#define QQ 128
#define MM 16
#define EPSF 1e-8f

// ---------------- scratch (static device allocations; no cudaMalloc) --------
__device__ float g_feat1[BB*NN*DD];
__device__ float g_k   [BB*NN*DD];   // pre-normalized k-hat
__device__ float g_q   [BB*NN*DD];   // pre-normalized q-hat
__device__ float g_w   [BB*NN*25];   // unnormalized exp(cos) weights, [b][pixel][tap]
__device__ float g_hA  [BB*NN*QQ];
__device__ float g_hB  [BB*NN*QQ];

// ---------------- conv1: (B,H,W,3) -> relu -> (B,H,W,32) --------------------
__global__ void conv1_k(const float* __restrict__ x,
                        const float* __restrict__ w,
                        const float* __restrict__ bias) {
    __shared__ float sw[3*3*3*32];
    __shared__ float sb[32];
    for (int t = threadIdx.x; t < 864; t += 512) sw[t] = w[t];
    if (threadIdx.x < 32) sb[threadIdx.x] = bias[threadIdx.x];
    __syncthreads();

    int gid = blockIdx.x * 16 + (threadIdx.x >> 5);   // pixel in [0, B*N)
    int co  = threadIdx.x & 31;
    int b = gid >> 14, p = gid & (NN-1);
    int i = p >> 7, j = p & 127;

    float acc = sb[co];
    #pragma unroll
    for (int ky = 0; ky < 3; ky++) {
        int yi = i + ky - 1;
        if ((unsigned)yi >= HH) continue;
        #pragma unroll
        for (int kx = 0; kx < 3; kx++) {
            int xj = j + kx - 1;
            if ((unsigned)xj >= WW) continue;
            const float* xp = x + ((size_t)((b << 14) | (yi << 7) | xj)) * 3;
            const float* wp = sw + (ky*3 + kx) * 3 * 32;
            #pragma unroll
            for (int ci = 0; ci < 3; ci++) acc += xp[ci] * wp[ci*32 + co];
        }
    }
    g_feat1[(size_t)gid*32 + co] = fmaxf(acc, 0.f);
}

// ------- conv2 + fused k/q projection + normalization (k-hat, q-hat) --------
__global__ void conv2kq_k(const float* __restrict__ w,
                          const float* __restrict__ bias,
                          const float* __restrict__ wk,
                          const float* __restrict__ bk,
                          const float* __restrict__ wq) {
    __shared__ float sw[3*3*32*32];
    __shared__ float swk[1024], swq[1024];
    __shared__ float sb[32], sbk[32];
    for (int t = threadIdx.x; t < 9216; t += 512) sw[t] = w[t];
    for (int t = threadIdx.x; t < 1024; t += 512) { swk[t] = wk[t]; swq[t] = wq[t]; }
    if (threadIdx.x < 32) { sb[threadIdx.x] = bias[threadIdx.x]; sbk[threadIdx.x] = bk[threadIdx.x]; }
    __syncthreads();

    int gid = blockIdx.x * 16 + (threadIdx.x >> 5);
    int co  = threadIdx.x & 31;
    int b = gid >> 14, p = gid & (NN-1);
    int i = p >> 7, j = p & 127;

    float acc = sb[co];
    #pragma unroll
    for (int ky = 0; ky < 3; ky++) {
        int yi = i + ky - 1;
        if ((unsigned)yi >= HH) continue;
        #pragma unroll
        for (int kx = 0; kx < 3; kx++) {
            int xj = j + kx - 1;
            if ((unsigned)xj >= WW) continue;
            const float* fin = g_feat1 + ((size_t)((b << 14) | (yi << 7) | xj)) * 32;
            const float* wp  = sw + (ky*3 + kx) * 32 * 32;
            #pragma unroll
            for (int ci = 0; ci < 32; ci++) acc += fin[ci] * wp[ci*32 + co];
        }
    }
    float fv = fmaxf(acc, 0.f);          // feat2 value for channel co (stays in reg)

    float ka = sbk[co], qa = 0.f;
    #pragma unroll
    for (int ci = 0; ci < 32; ci++) {
        float f = __shfl_sync(0xffffffffu, fv, ci);
        ka += f * swk[ci*32 + co];
        qa += f * swq[ci*32 + co];
    }
    float ks = ka*ka, qs = qa*qa;
    #pragma unroll
    for (int o = 16; o; o >>= 1) {
        ks += __shfl_xor_sync(0xffffffffu, ks, o);
        qs += __shfl_xor_sync(0xffffffffu, qs, o);
    }
    // pre-normalize: cosine sim becomes a plain dot product downstream.
    float kinv = rsqrtf(fmaxf(ks, 1e-30f));
    float qinv = rsqrtf(fmaxf(qs, 1e-30f));
    g_k[(size_t)gid*32 + co] = ka * kinv;
    g_q[(size_t)gid*32 + co] = qa * qinv;
}

// ---------------- edge weights: exp(dot(q-hat, k-hat)), tile-based ----------
__global__ void edgew_k() {
    __shared__ float sk[32*145];    // [c][halo_pixel], padded stride
    __shared__ float sq[64*32];     // [tile_pixel][c]

    int b = blockIdx.z;
    int ti0 = blockIdx.y << 3, tj0 = blockIdx.x << 3;
    int tid = threadIdx.x;
    size_t bbase = (size_t)b << 14;

    // k halo: 144 pixels x 32 ch, transposed on the fly
    for (int t = tid; t < 1152; t += 256) {
        int hp = t >> 3, c4 = t & 7;
        int hr = hp / 12, hc = hp - hr*12;
        int gi = min(max(ti0 + hr - 2, 0), HH-1);
        int gj = min(max(tj0 + hc - 2, 0), WW-1);
        float4 v = ((const float4*)(g_k + (bbase + (gi << 7) + gj) * 32))[c4];
        sk[(c4*4+0)*145 + hp] = v.x;
        sk[(c4*4+1)*145 + hp] = v.y;
        sk[(c4*4+2)*145 + hp] = v.z;
        sk[(c4*4+3)*145 + hp] = v.w;
    }
    // q tile: 64 pixels x 32 ch, straight
    for (int t = tid; t < 512; t += 256) {
        int p = t >> 3, c4 = t & 7;
        int gi = ti0 + (p >> 3), gj = tj0 + (p & 7);
        ((float4*)sq)[t] = ((const float4*)(g_q + (bbase + (gi << 7) + gj) * 32))[c4];
    }
    __syncthreads();

    int lane = tid & 31, a = tid >> 5;          // warp = tile row a
    int d = min(lane, 24);
    int dr = d / 5, dc = d - dr*5;

    for (int cc = 0; cc < 8; cc++) {
        int p = a*8 + cc;
        int hidx = (a + dr)*12 + (cc + dc);
        const float* skp = sk + hidx;
        const float* sqp = sq + p*32;
        float s = 0.f;
        #pragma unroll
        for (int c = 0; c < 32; c++) s += sqp[c] * skp[c*145];
        if (lane < 25) {
            size_t gp = bbase + ((ti0 + a) << 7) + (tj0 + cc);
            g_w[gp*25 + lane] = __expf(s);
        }
    }
}

// ---------------- propagation: weighted 5x5 stencil + L2-normalize ----------
// 8x8 tile / block; 128 channels processed as TWO sequential 64-ch chunks that
// reuse one 12x12x64 halo buffer (36.9KB) + (w,w)-dup weights (12.8KB) =
// 49.7KB smem -> 4 blocks/SM (was 2). Warp = tile column, lane = one f32x2
// channel pair; warp slides down 12 halo rows accumulating all 8 output rows
// (each halo LDS.64 reused up to 5x, feeding fma.rn.f32x2 directly).
#define PROP_SMEM_FLOATS (144*64 + 64*25*2)
__global__ __launch_bounds__(256, 4) void prop_k(const float* __restrict__ hinit, int it) {
    extern __shared__ float sh[];                    // halo: 144 px x 32 float2
    float* shw = sh + 144*64;                        // weights: 64 px x 25 (w,w)

    const float* hin = (it == 0) ? hinit : ((it & 1) ? g_hA : g_hB);
    float*       hout = (it & 1) ? g_hB : g_hA;

    int b = blockIdx.z;
    int ti0 = blockIdx.y << 3, tj0 = blockIdx.x << 3;
    int tid = threadIdx.x;
    int lane = tid & 31, c = tid >> 5;               // warp = tile column

    const float* hb = hin + ((size_t)b << 21);       // b*N*128
    float* hob = hout + ((size_t)b << 21);

    // weights once (valid across both chunks)
    const float* wb = g_w + ((size_t)b << 14) * 25;
    for (int t = tid; t < 1600; t += 256) {
        int op = t / 25, d = t - op*25;
        int a = op >> 3, cc = op & 7;
        float w = wb[(size_t)(((ti0 + a) << 7) | (tj0 + cc)) * 25 + d];
        ((float2*)shw)[t] = make_float2(w, w);
    }

    const unsigned long long* sh64  = (const unsigned long long*)sh;
    const unsigned long long* shw64 = (const unsigned long long*)shw;

    unsigned long long acc[2][8];

    #pragma unroll
    for (int chunk = 0; chunk < 2; chunk++) {
        if (chunk) __syncthreads();                  // protect halo before overwrite
        // halo for this 64-ch chunk: 144 px x 16 float4
        for (int t = tid; t < 144*16; t += 256) {
            int prow = t >> 4, f4 = t & 15;
            int hr = prow / 12, hc = prow - hr*12;
            int gi = min(max(ti0 + hr - 2, 0), HH-1);
            int gj = min(max(tj0 + hc - 2, 0), WW-1);
            ((float4*)sh)[t] =
                ((const float4*)(hb + ((size_t)((gi << 7) + gj) << 7) + chunk*64))[f4];
        }
        __syncthreads();

        #pragma unroll
        for (int a = 0; a < 8; a++) acc[chunk][a] = 0ull;

        #pragma unroll
        for (int dj = 0; dj < 5; dj++) {
            int hc = c + dj;
            #pragma unroll
            for (int hr = 0; hr < 12; hr++) {
                unsigned long long h = sh64[(hr*12 + hc)*32 + lane];
                #pragma unroll
                for (int a = 0; a < 8; a++) {
                    if (a > hr || a + 4 < hr) continue;      // compile-time pruned
                    unsigned long long ww = shw64[(a*8 + c)*25 + (hr - a)*5 + dj];
                    asm("fma.rn.f32x2 %0, %1, %2, %0;"
                        : "+l"(acc[chunk][a]) : "l"(h), "l"(ww));
                }
            }
        }
    }

    #pragma unroll
    for (int a = 0; a < 8; a++) {
        float x0, y0, x1, y1;
        asm("mov.b64 {%0,%1}, %2;" : "=f"(x0), "=f"(y0) : "l"(acc[0][a]));
        asm("mov.b64 {%0,%1}, %2;" : "=f"(x1), "=f"(y1) : "l"(acc[1][a]));
        float ss = x0*x0 + y0*y0 + x1*x1 + y1*y1;
        #pragma unroll
        for (int o = 16; o; o >>= 1) ss += __shfl_xor_sync(0xffffffffu, ss, o);
        float inv = 1.f / (sqrtf(ss) + EPSF);
        float* po = hob + ((size_t)(((ti0 + a) << 7) | (tj0 + c)) << 7);
        ((float2*)po)[lane]      = make_float2(x0*inv, y0*inv);
        ((float2*)po)[32 + lane] = make_float2(x1*inv, y1*inv);
    }
}

// ---------------- mask head: h @ w_mask, softmax over M, NCHW out -----------
__global__ void masks_k(const float* __restrict__ wm, float* __restrict__ out) {
    __shared__ float swm[QQ*MM];
    for (int t = threadIdx.x; t < QQ*MM; t += 256) swm[t] = wm[t];
    __syncthreads();

    int gid = blockIdx.x * 256 + threadIdx.x;   // [0, B*N)
    int b = gid >> 14, p = gid & (NN-1);
    const float* hr = g_hB + (size_t)gid * QQ;  // 32 iterations -> final in hB

    float lg[MM];
    #pragma unroll
    for (int m = 0; m < MM; m++) lg[m] = 0.f;
    for (int q = 0; q < QQ; q++) {
        float hv = hr[q];
        #pragma unroll
        for (int m = 0; m < MM; m++) lg[m] += hv * swm[q*MM + m];
    }
    float mx = lg[0];
    #pragma unroll
    for (int m = 1; m < MM; m++) mx = fmaxf(mx, lg[m]);
    float s = 0.f;
    #pragma unroll
    for (int m = 0; m < MM; m++) { lg[m] = __expf(lg[m] - mx); s += lg[m]; }
    float r = 1.f / s;
    #pragma unroll
    for (int m = 0; m < MM; m++)
        out[(((size_t)(b*MM + m)) << 14) + p] = lg[m] * r;
}

// ---------------- launch ----------------------------------------------------
extern "C" void kernel_launch(void* const* d_in, const int* in_sizes, int n_in,
                              void* d_out, int out_size) {
    const float* x    = (const float*)d_in[0];
    // d_in[1] = edges (int32) — edge structure is analytic, unused
    const float* wc1  = (const float*)d_in[2];
    const float* bc1  = (const float*)d_in[3];
    const float* wc2  = (const float*)d_in[4];
    const float* bc2  = (const float*)d_in[5];
    const float* wk   = (const float*)d_in[6];
    const float* bk   = (const float*)d_in[7];
    const float* wq   = (const float*)d_in[8];
    const float* init = (const float*)d_in[9];
    const float* wm   = (const float*)d_in[10];
    float* out = (float*)d_out;

    cudaFuncSetAttribute(prop_k, cudaFuncAttributeMaxDynamicSharedMemorySize,
                         PROP_SMEM_FLOATS * (int)sizeof(float));

    conv1_k  <<<BB*NN*32/512, 512>>>(x, wc1, bc1);
    conv2kq_k<<<BB*NN*32/512, 512>>>(wc2, bc2, wk, bk, wq);
    edgew_k  <<<dim3(WW/8, HH/8, BB), 256>>>();

    for (int it = 0; it < 32; it++) {
        prop_k<<<dim3(WW/8, HH/8, BB), 256,
                 PROP_SMEM_FLOATS * sizeof(float)>>>(init, it);
    }
    masks_k<<<BB*NN/256, 256>>>(wm, out);
}

// round 5
// speedup vs baseline: 1.8213x; 1.0874x over previous
#include <cuda_runtime.h>
#include <math.h>

#define HH 128
#define WW 128
#define NN 16384          // H*W
#define BB 2
#define DD 32
#define QQ 128
#define MM 16
#define EPSF 1e-8f

// ---------------- scratch (static device allocations; no cudaMalloc) --------
__device__ float g_feat1[BB*NN*DD];
__device__ float g_k   [BB*NN*DD];   // pre-normalized k-hat
__device__ float g_q   [BB*NN*DD];   // pre-normalized q-hat
__device__ float g_w   [BB*NN*25];   // unnormalized exp(cos) weights, [b][pixel][tap]
__device__ float g_hA  [BB*NN*QQ];
__device__ float g_hB  [BB*NN*QQ];

// ---------------- conv1: (B,H,W,3) -> relu -> (B,H,W,32) --------------------
__global__ void conv1_k(const float* __restrict__ x,
                        const float* __restrict__ w,
                        const float* __restrict__ bias) {
    __shared__ float sw[3*3*3*32];
    __shared__ float sb[32];
    for (int t = threadIdx.x; t < 864; t += 512) sw[t] = w[t];
    if (threadIdx.x < 32) sb[threadIdx.x] = bias[threadIdx.x];
    __syncthreads();

    int gid = blockIdx.x * 16 + (threadIdx.x >> 5);   // pixel in [0, B*N)
    int co  = threadIdx.x & 31;
    int b = gid >> 14, p = gid & (NN-1);
    int i = p >> 7, j = p & 127;

    float acc = sb[co];
    #pragma unroll
    for (int ky = 0; ky < 3; ky++) {
        int yi = i + ky - 1;
        if ((unsigned)yi >= HH) continue;
        #pragma unroll
        for (int kx = 0; kx < 3; kx++) {
            int xj = j + kx - 1;
            if ((unsigned)xj >= WW) continue;
            const float* xp = x + ((size_t)((b << 14) | (yi << 7) | xj)) * 3;
            const float* wp = sw + (ky*3 + kx) * 3 * 32;
            #pragma unroll
            for (int ci = 0; ci < 3; ci++) acc += xp[ci] * wp[ci*32 + co];
        }
    }
    g_feat1[(size_t)gid*32 + co] = fmaxf(acc, 0.f);
}

// ------- conv2 + fused k/q projection + normalization (k-hat, q-hat) --------
__global__ void conv2kq_k(const float* __restrict__ w,
                          const float* __restrict__ bias,
                          const float* __restrict__ wk,
                          const float* __restrict__ bk,
                          const float* __restrict__ wq) {
    __shared__ float sw[3*3*32*32];
    __shared__ float swk[1024], swq[1024];
    __shared__ float sb[32], sbk[32];
    for (int t = threadIdx.x; t < 9216; t += 512) sw[t] = w[t];
    for (int t = threadIdx.x; t < 1024; t += 512) { swk[t] = wk[t]; swq[t] = wq[t]; }
    if (threadIdx.x < 32) { sb[threadIdx.x] = bias[threadIdx.x]; sbk[threadIdx.x] = bk[threadIdx.x]; }
    __syncthreads();

    int gid = blockIdx.x * 16 + (threadIdx.x >> 5);
    int co  = threadIdx.x & 31;
    int b = gid >> 14, p = gid & (NN-1);
    int i = p >> 7, j = p & 127;

    float acc = sb[co];
    #pragma unroll
    for (int ky = 0; ky < 3; ky++) {
        int yi = i + ky - 1;
        if ((unsigned)yi >= HH) continue;
        #pragma unroll
        for (int kx = 0; kx < 3; kx++) {
            int xj = j + kx - 1;
            if ((unsigned)xj >= WW) continue;
            const float* fin = g_feat1 + ((size_t)((b << 14) | (yi << 7) | xj)) * 32;
            const float* wp  = sw + (ky*3 + kx) * 32 * 32;
            #pragma unroll
            for (int ci = 0; ci < 32; ci++) acc += fin[ci] * wp[ci*32 + co];
        }
    }
    float fv = fmaxf(acc, 0.f);          // feat2 value for channel co (stays in reg)

    float ka = sbk[co], qa = 0.f;
    #pragma unroll
    for (int ci = 0; ci < 32; ci++) {
        float f = __shfl_sync(0xffffffffu, fv, ci);
        ka += f * swk[ci*32 + co];
        qa += f * swq[ci*32 + co];
    }
    float ks = ka*ka, qs = qa*qa;
    #pragma unroll
    for (int o = 16; o; o >>= 1) {
        ks += __shfl_xor_sync(0xffffffffu, ks, o);
        qs += __shfl_xor_sync(0xffffffffu, qs, o);
    }
    // pre-normalize: cosine sim becomes a plain dot product downstream.
    float kinv = rsqrtf(fmaxf(ks, 1e-30f));
    float qinv = rsqrtf(fmaxf(qs, 1e-30f));
    g_k[(size_t)gid*32 + co] = ka * kinv;
    g_q[(size_t)gid*32 + co] = qa * qinv;
}

// ---------------- edge weights: exp(dot(q-hat, k-hat)), tile-based ----------
__global__ void edgew_k() {
    __shared__ float sk[32*145];    // [c][halo_pixel], padded stride
    __shared__ float sq[64*32];     // [tile_pixel][c]

    int b = blockIdx.z;
    int ti0 = blockIdx.y << 3, tj0 = blockIdx.x << 3;
    int tid = threadIdx.x;
    size_t bbase = (size_t)b << 14;

    // k halo: 144 pixels x 32 ch, transposed on the fly
    for (int t = tid; t < 1152; t += 256) {
        int hp = t >> 3, c4 = t & 7;
        int hr = hp / 12, hc = hp - hr*12;
        int gi = min(max(ti0 + hr - 2, 0), HH-1);
        int gj = min(max(tj0 + hc - 2, 0), WW-1);
        float4 v = ((const float4*)(g_k + (bbase + (gi << 7) + gj) * 32))[c4];
        sk[(c4*4+0)*145 + hp] = v.x;
        sk[(c4*4+1)*145 + hp] = v.y;
        sk[(c4*4+2)*145 + hp] = v.z;
        sk[(c4*4+3)*145 + hp] = v.w;
    }
    // q tile: 64 pixels x 32 ch, straight
    for (int t = tid; t < 512; t += 256) {
        int p = t >> 3, c4 = t & 7;
        int gi = ti0 + (p >> 3), gj = tj0 + (p & 7);
        ((float4*)sq)[t] = ((const float4*)(g_q + (bbase + (gi << 7) + gj) * 32))[c4];
    }
    __syncthreads();

    int lane = tid & 31, a = tid >> 5;          // warp = tile row a
    int d = min(lane, 24);
    int dr = d / 5, dc = d - dr*5;

    for (int cc = 0; cc < 8; cc++) {
        int p = a*8 + cc;
        int hidx = (a + dr)*12 + (cc + dc);
        const float* skp = sk + hidx;
        const float* sqp = sq + p*32;
        float s = 0.f;
        #pragma unroll
        for (int c = 0; c < 32; c++) s += sqp[c] * skp[c*145];
        if (lane < 25) {
            size_t gp = bbase + ((ti0 + a) << 7) + (tj0 + cc);
            g_w[gp*25 + lane] = __expf(s);
        }
    }
}

// ---------------- propagation: weighted 5x5 stencil + L2-normalize ----------
// 8x8 tile / block; 128 channels as TWO sequential 64-ch chunks sharing one
// 12x12x64 halo (36.9KB). Weights stored SCALAR, row-padded to 8 floats
// (op*40 + taprow*8 + tapcol): each (output, halo-row) fetches its 5-tap row
// as one LDS.128 + one LDS.32 (2 broadcast wavefronts instead of 5); f32x2
// duplication happens in registers (ALU mov.b64). hr-outer loop keeps the 5
// h-values (dj=0..4) cached in registers across the output window.
#define PROP_SMEM_FLOATS (144*64 + 64*40)
__global__ __launch_bounds__(256, 4) void prop_k(const float* __restrict__ hinit, int it) {
    extern __shared__ float sh[];                    // halo: 144 px x 32 float2
    float* shw = sh + 144*64;                        // weights: 64 px x 40 floats

    const float* hin = (it == 0) ? hinit : ((it & 1) ? g_hA : g_hB);
    float*       hout = (it & 1) ? g_hB : g_hA;

    int b = blockIdx.z;
    int ti0 = blockIdx.y << 3, tj0 = blockIdx.x << 3;
    int tid = threadIdx.x;
    int lane = tid & 31, c = tid >> 5;               // warp = tile column

    const float* hb = hin + ((size_t)b << 21);       // b*N*128
    float* hob = hout + ((size_t)b << 21);

    // stage weights once (valid across both chunks), row-padded scalar layout
    const float* wb = g_w + ((size_t)b << 14) * 25;
    for (int t = tid; t < 1600; t += 256) {
        int op = t / 25, d = t - op*25;
        int a = op >> 3, cc = op & 7;
        int r = d / 5, cl = d - r*5;
        shw[op*40 + r*8 + cl] =
            wb[(size_t)(((ti0 + a) << 7) | (tj0 + cc)) * 25 + d];
    }

    const unsigned long long* sh64 = (const unsigned long long*)sh;

    unsigned long long acc[2][8];

    #pragma unroll
    for (int chunk = 0; chunk < 2; chunk++) {
        if (chunk) __syncthreads();                  // protect halo before overwrite
        // halo for this 64-ch chunk: 144 px x 16 float4
        for (int t = tid; t < 144*16; t += 256) {
            int prow = t >> 4, f4 = t & 15;
            int hr = prow / 12, hc = prow - hr*12;
            int gi = min(max(ti0 + hr - 2, 0), HH-1);
            int gj = min(max(tj0 + hc - 2, 0), WW-1);
            ((float4*)sh)[t] =
                ((const float4*)(hb + ((size_t)((gi << 7) + gj) << 7) + chunk*64))[f4];
        }
        __syncthreads();

        #pragma unroll
        for (int a = 0; a < 8; a++) acc[chunk][a] = 0ull;

        #pragma unroll
        for (int hr = 0; hr < 12; hr++) {
            // cache the 5 halo values (dj = 0..4) for this row in registers
            unsigned long long hv[5];
            #pragma unroll
            for (int dj = 0; dj < 5; dj++)
                hv[dj] = sh64[(hr*12 + c + dj)*32 + lane];

            #pragma unroll
            for (int a = 0; a < 8; a++) {
                if (a > hr || a + 4 < hr) continue;      // compile-time pruned
                const float* wr = shw + (a*8 + c)*40 + (hr - a)*8;
                float4 w03 = *(const float4*)wr;         // taps 0-3 (16B aligned)
                float  w4  = wr[4];                      // tap 4
                unsigned long long W0, W1, W2, W3, W4;
                asm("mov.b64 %0,{%1,%1};" : "=l"(W0) : "f"(w03.x));
                asm("mov.b64 %0,{%1,%1};" : "=l"(W1) : "f"(w03.y));
                asm("mov.b64 %0,{%1,%1};" : "=l"(W2) : "f"(w03.z));
                asm("mov.b64 %0,{%1,%1};" : "=l"(W3) : "f"(w03.w));
                asm("mov.b64 %0,{%1,%1};" : "=l"(W4) : "f"(w4));
                asm("fma.rn.f32x2 %0, %1, %2, %0;" : "+l"(acc[chunk][a]) : "l"(hv[0]), "l"(W0));
                asm("fma.rn.f32x2 %0, %1, %2, %0;" : "+l"(acc[chunk][a]) : "l"(hv[1]), "l"(W1));
                asm("fma.rn.f32x2 %0, %1, %2, %0;" : "+l"(acc[chunk][a]) : "l"(hv[2]), "l"(W2));
                asm("fma.rn.f32x2 %0, %1, %2, %0;" : "+l"(acc[chunk][a]) : "l"(hv[3]), "l"(W3));
                asm("fma.rn.f32x2 %0, %1, %2, %0;" : "+l"(acc[chunk][a]) : "l"(hv[4]), "l"(W4));
            }
        }
    }

    #pragma unroll
    for (int a = 0; a < 8; a++) {
        float x0, y0, x1, y1;
        asm("mov.b64 {%0,%1}, %2;" : "=f"(x0), "=f"(y0) : "l"(acc[0][a]));
        asm("mov.b64 {%0,%1}, %2;" : "=f"(x1), "=f"(y1) : "l"(acc[1][a]));
        float ss = x0*x0 + y0*y0 + x1*x1 + y1*y1;
        #pragma unroll
        for (int o = 16; o; o >>= 1) ss += __shfl_xor_sync(0xffffffffu, ss, o);
        float inv = 1.f / (sqrtf(ss) + EPSF);
        float* po = hob + ((size_t)(((ti0 + a) << 7) | (tj0 + c)) << 7);
        ((float2*)po)[lane]      = make_float2(x0*inv, y0*inv);
        ((float2*)po)[32 + lane] = make_float2(x1*inv, y1*inv);
    }
}

// ---------------- mask head: h @ w_mask, softmax over M, NCHW out -----------
__global__ void masks_k(const float* __restrict__ wm, float* __restrict__ out) {
    __shared__ float swm[QQ*MM];
    for (int t = threadIdx.x; t < QQ*MM; t += 256) swm[t] = wm[t];
    __syncthreads();

    int gid = blockIdx.x * 256 + threadIdx.x;   // [0, B*N)
    int b = gid >> 14, p = gid & (NN-1);
    const float* hr = g_hB + (size_t)gid * QQ;  // 32 iterations -> final in hB

    float lg[MM];
    #pragma unroll
    for (int m = 0; m < MM; m++) lg[m] = 0.f;
    for (int q = 0; q < QQ; q++) {
        float hv = hr[q];
        #pragma unroll
        for (int m = 0; m < MM; m++) lg[m] += hv * swm[q*MM + m];
    }
    float mx = lg[0];
    #pragma unroll
    for (int m = 1; m < MM; m++) mx = fmaxf(mx, lg[m]);
    float s = 0.f;
    #pragma unroll
    for (int m = 0; m < MM; m++) { lg[m] = __expf(lg[m] - mx); s += lg[m]; }
    float r = 1.f / s;
    #pragma unroll
    for (int m = 0; m < MM; m++)
        out[(((size_t)(b*MM + m)) << 14) + p] = lg[m] * r;
}

// ---------------- launch ----------------------------------------------------
extern "C" void kernel_launch(void* const* d_in, const int* in_sizes, int n_in,
                              void* d_out, int out_size) {
    const float* x    = (const float*)d_in[0];
    // d_in[1] = edges (int32) — edge structure is analytic, unused
    const float* wc1  = (const float*)d_in[2];
    const float* bc1  = (const float*)d_in[3];
    const float* wc2  = (const float*)d_in[4];
    const float* bc2  = (const float*)d_in[5];
    const float* wk   = (const float*)d_in[6];
    const float* bk   = (const float*)d_in[7];
    const float* wq   = (const float*)d_in[8];
    const float* init = (const float*)d_in[9];
    const float* wm   = (const float*)d_in[10];
    float* out = (float*)d_out;

    cudaFuncSetAttribute(prop_k, cudaFuncAttributeMaxDynamicSharedMemorySize,
                         PROP_SMEM_FLOATS * (int)sizeof(float));

    conv1_k  <<<BB*NN*32/512, 512>>>(x, wc1, bc1);
    conv2kq_k<<<BB*NN*32/512, 512>>>(wc2, bc2, wk, bk, wq);
    edgew_k  <<<dim3(WW/8, HH/8, BB), 256>>>();

    for (int it = 0; it < 32; it++) {
        prop_k<<<dim3(WW/8, HH/8, BB), 256,
                 PROP_SMEM_FLOATS * sizeof(float)>>>(init, it);
    }
    masks_k<<<BB*NN/256, 256>>>(wm, out);
}